// round 1
// baseline (speedup 1.0000x reference)
#include <cuda_runtime.h>
#include <math.h>

// Problem dims (fixed by the reference):
//   inputs  : (4, 2, 96, 192, 192) float32
//   targets : (4, 1, 96, 192, 192) int32
#define Bn   4
#define Zd   96
#define Yd   192
#define Xd   192
#define YX   (Yd * Xd)            // 36864
#define WX   3                    // 192 bits = 3 x uint64 per row
#define ROWS (Bn * Zd * Yd)       // 73728
#define WORDS (ROWS * WX)         // 221184 words per field
#define NVOX (Bn * Zd * YX)       // 14155776
#define ITERS 20

// Bit fields: [parity][field][word]; field 0 = t, field 1 = 1 - t.
__device__ unsigned long long g_bits[2][2][WORDS];   // ~7.1 MB
__device__ double g_S0[Bn];     // sum p * t           per batch
__device__ double g_Sp[Bn];     // sum p               per batch
__device__ double g_accA[Bn];   // sum_i sum_{alive_i(t)} p
__device__ double g_accB[Bn];   // sum_i sum_{alive_i(1-t)} p
__device__ int    g_fg[Bn];     // foreground voxel count per batch
__device__ int    g_nz[ITERS + 1][2];  // nonzero-word count per iteration per field

__global__ void k_zero() {
    int t = threadIdx.x;
    if (t < Bn) {
        g_S0[t] = 0.0; g_Sp[t] = 0.0; g_accA[t] = 0.0; g_accB[t] = 0.0;
        g_fg[t] = 0;
    }
    if (t < (ITERS + 1) * 2) ((int*)g_nz)[t] = 0;
}

// Pack targets into bits (t and ~t), count fg per batch, and compute
// S0 = sum(p*t), Sp = sum(p) per batch. One block per (b, z) slice.
__global__ void __launch_bounds__(256) k_pack(const float* __restrict__ inp,
                                              const int* __restrict__ tgt) {
    int slice = blockIdx.x;            // b*Zd + z
    int b = slice / Zd;
    int tid = threadIdx.x;
    int lane = tid & 31;
    int warp = tid >> 5;

    long tbase = (long)slice * YX;
    long in0 = ((long)(b * 2)) * (long)Zd * YX + (long)(slice % Zd) * YX;
    long in1 = in0 + (long)Zd * YX;

    unsigned int* b0 = (unsigned int*)g_bits[0][0];
    unsigned int* b1 = (unsigned int*)g_bits[0][1];

    float s0 = 0.0f, sp = 0.0f;
    int fg = 0;
    int nz0 = 0, nz1 = 0;

    for (int base = 0; base < YX; base += 256) {
        int v = base + tid;
        int tv = tgt[tbase + v];
        unsigned m = __ballot_sync(0xffffffffu, tv != 0);
        float x0 = inp[in0 + v];
        float x1 = inp[in1 + v];
        float p = 1.0f / (1.0f + __expf(x0 - x1));   // softmax channel 1
        sp += p;
        if (tv) s0 += p;
        if (lane == 0) {
            long wi = (tbase + v) >> 5;
            b0[wi] = m;
            b1[wi] = ~m;
            fg += __popc(m);
            if (m) nz0 = 1;
            if (~m) nz1 = 1;
        }
    }

    // block reduction
    #pragma unroll
    for (int o = 16; o > 0; o >>= 1) {
        s0 += __shfl_down_sync(0xffffffffu, s0, o);
        sp += __shfl_down_sync(0xffffffffu, sp, o);
    }
    __shared__ float sh0[8], shp[8];
    __shared__ int shfg, shn0, shn1;
    if (tid == 0) { shfg = 0; shn0 = 0; shn1 = 0; }
    __syncthreads();
    if (lane == 0) {
        sh0[warp] = s0; shp[warp] = sp;
        atomicAdd(&shfg, fg);
        if (nz0) shn0 = 1;
        if (nz1) shn1 = 1;
    }
    __syncthreads();
    if (tid == 0) {
        float t0 = 0.0f, tp = 0.0f;
        #pragma unroll
        for (int w = 0; w < 8; w++) { t0 += sh0[w]; tp += shp[w]; }
        atomicAdd(&g_S0[b], (double)t0);
        atomicAdd(&g_Sp[b], (double)tp);
        atomicAdd(&g_fg[b], shfg);
        if (shn0) atomicAdd(&g_nz[0][0], 1);
        if (shn1) atomicAdd(&g_nz[0][1], 1);
    }
}

// One erosion iteration for both fields. One thread per output word.
// Early-exits per field once the alive set is empty.
__global__ void __launch_bounds__(256) k_erode(const float* __restrict__ inp, int it) {
    int par = (it - 1) & 1;
    long gw = (long)blockIdx.x * 256 + threadIdx.x;   // 0 .. 2*WORDS-1
    int f = (int)(gw / WORDS);                        // uniform per block (WORDS % 256 == 0)
    if (g_nz[it - 1][f] == 0) return;                 // nothing alive -> erosion stays empty

    int lw = (int)(gw % WORDS);
    int r  = lw / WX;
    int k  = lw % WX;
    int b  = r / (Zd * Yd);
    int zz = (r / Yd) % Zd;
    int yy = r % Yd;

    const unsigned long long* cur = g_bits[par][f];
    unsigned long long acc = ~0ULL;
    #pragma unroll
    for (int dz = -1; dz <= 1; dz++) {
        int z2 = zz + dz;
        if ((unsigned)z2 >= (unsigned)Zd) continue;   // out of domain == all ones
        #pragma unroll
        for (int dy = -1; dy <= 1; dy++) {
            int y2 = yy + dy;
            if ((unsigned)y2 >= (unsigned)Yd) continue;
            int rb = ((b * Zd + z2) * Yd + y2) * WX;
            unsigned long long c  = cur[rb + k];
            unsigned long long lt = (k > 0)  ? cur[rb + k - 1] : ~0ULL;
            unsigned long long rt = (k < 2)  ? cur[rb + k + 1] : ~0ULL;
            acc &= c & ((c >> 1) | (rt << 63)) & ((c << 1) | (lt >> 63));
        }
    }
    g_bits[par ^ 1][f][lw] = acc;

    // p-weighted popcount of surviving voxels (sparse; empty after iter 1 typically)
    float s = 0.0f;
    if (acc) {
        long in0 = ((long)(b * 2)) * (long)Zd * YX + (long)zz * YX + (long)yy * Xd + k * 64;
        long in1 = in0 + (long)Zd * YX;
        unsigned long long m = acc;
        while (m) {
            int j = __ffsll((long long)m) - 1;
            m &= m - 1;
            float x0 = inp[in0 + j];
            float x1 = inp[in1 + j];
            s += 1.0f / (1.0f + __expf(x0 - x1));
        }
    }

    int any = __syncthreads_or(acc != 0ULL);

    #pragma unroll
    for (int o = 16; o > 0; o >>= 1)
        s += __shfl_down_sync(0xffffffffu, s, o);
    __shared__ float sh[8];
    int tid = threadIdx.x, lane = tid & 31, warp = tid >> 5;
    if (lane == 0) sh[warp] = s;
    __syncthreads();
    if (tid == 0) {
        float tot = 0.0f;
        #pragma unroll
        for (int w = 0; w < 8; w++) tot += sh[w];
        if (tot != 0.0f)
            atomicAdd(f ? &g_accB[b] : &g_accA[b], (double)tot);
        if (any) atomicAdd(&g_nz[it][f], 1);
    }
}

__global__ void k_final(float* out) {
    if (threadIdx.x == 0) {
        double tot = 0.0;
        #pragma unroll
        for (int b = 0; b < Bn; b++) {
            double v = (g_fg[b] == 0) ? g_Sp[b]
                                      : (g_S0[b] - g_accA[b] + g_accB[b]);
            tot += v;
        }
        out[0] = (float)(tot / (double)NVOX);
    }
}

extern "C" void kernel_launch(void* const* d_in, const int* in_sizes, int n_in,
                              void* d_out, int out_size) {
    // inputs (2*NVOX floats) first, targets (NVOX ints) second; guard by size.
    const float* inp;
    const int*   tgt;
    if (in_sizes[0] >= in_sizes[1]) {
        inp = (const float*)d_in[0];
        tgt = (const int*)d_in[1];
    } else {
        inp = (const float*)d_in[1];
        tgt = (const int*)d_in[0];
    }

    k_zero<<<1, 64>>>();
    k_pack<<<Bn * Zd, 256>>>(inp, tgt);
    for (int it = 1; it <= ITERS; it++)
        k_erode<<<(2 * WORDS) / 256, 256>>>(inp, it);
    k_final<<<1, 32>>>((float*)d_out);
}

// round 2
// speedup vs baseline: 2.1548x; 2.1548x over previous
#include <cuda_runtime.h>
#include <math.h>

// Problem dims (fixed by the reference):
//   inputs  : (4, 2, 96, 192, 192) float32
//   targets : (4, 1, 96, 192, 192) int32
#define Bn   4
#define Zd   96
#define Yd   192
#define Xd   192
#define YX   (Yd * Xd)            // 36864
#define WX   3                    // 192 bits = 3 x uint64 per row
#define ROWS (Bn * Zd * Yd)       // 73728
#define WORDS (ROWS * WX)         // 221184 words per field
#define NVOX (Bn * Zd * YX)       // 14155776
#define BVOX ((long)Zd * YX)      // voxels per (b, c) volume
#define ITERS 20

// Fused-erosion tiling: 4 iterations per launch, halo 4.
#define ZT 16
#define YT 16
#define H  4
#define SZ (ZT + 2 * H)           // 24
#define SY (YT + 2 * H)           // 24
#define TW (SZ * SY * WX)         // 1728 words per tile buffer
#define TILES_Z (Zd / ZT)         // 6
#define TILES_Y (Yd / YT)         // 12
#define TILES_PER_B (TILES_Z * TILES_Y)      // 72
#define BLOCKS_PER_F (Bn * TILES_PER_B)      // 288
#define NGROUPS (ITERS / 4)       // 5

// Pack kernel chunking
#define PCH 2048
#define PACK_BLOCKS (NVOX / PCH)  // 6912

// Bit fields: [parity][field][word]; field 0 = t, field 1 = 1 - t.
__device__ unsigned long long g_bits[2][2][WORDS];   // ~7.1 MB
__device__ double g_S0[Bn];     // sum p * t           per batch
__device__ double g_Sp[Bn];     // sum p               per batch
__device__ double g_accA[Bn];   // sum_i sum_{alive_i(t)} p
__device__ double g_accB[Bn];   // sum_i sum_{alive_i(1-t)} p
__device__ int    g_fg[Bn];     // foreground voxel count per batch
__device__ int    g_flag[NGROUPS + 1][2];  // [0] after pack, [g+1] after group g

__global__ void k_zero() {
    int t = threadIdx.x;
    if (t < Bn) {
        g_S0[t] = 0.0; g_Sp[t] = 0.0; g_accA[t] = 0.0; g_accB[t] = 0.0;
        g_fg[t] = 0;
    }
    if (t < (NGROUPS + 1) * 2) ((int*)g_flag)[t] = 0;
}

__device__ __forceinline__ float sig_p(float x0, float x1) {
    // softmax channel 1 of {x0, x1} = 1 / (1 + exp(x0 - x1))
    return __fdividef(1.0f, 1.0f + __expf(x0 - x1));
}

// Pack targets into bits (t and ~t), count fg per batch, and compute
// S0 = sum(p*t), Sp = sum(p) per batch. One block per 2048-voxel chunk.
__global__ void __launch_bounds__(256) k_pack(const float* __restrict__ inp,
                                              const int* __restrict__ tgt) {
    long base = (long)blockIdx.x * PCH;
    int b = (int)(base / BVOX);          // uniform per block (BVOX % PCH == 0)
    long vloc = base - (long)b * BVOX;

    const float* p0 = inp + (long)b * 2 * BVOX + vloc;
    const float* p1 = p0 + BVOX;
    const int*   tg = tgt + base;
    unsigned int* w0 = ((unsigned int*)g_bits[0][0]) + (base >> 5);
    unsigned int* w1 = ((unsigned int*)g_bits[0][1]) + (base >> 5);

    int tid = threadIdx.x;
    int lane = tid & 31;
    int warp = tid >> 5;

    float s0 = 0.0f, sp = 0.0f;
    int fg = 0, nz0 = 0, nz1 = 0;

    #pragma unroll
    for (int i = 0; i < PCH / 256; i++) {
        int v = i * 256 + tid;
        int tv = tg[v];
        float x0 = p0[v];
        float x1 = p1[v];
        unsigned m = __ballot_sync(0xffffffffu, tv != 0);
        float p = sig_p(x0, x1);
        sp += p;
        if (tv) s0 += p;
        if (lane == 0) {
            int wi = i * 8 + warp;
            w0[wi] = m;
            w1[wi] = ~m;
            fg += __popc(m);
            if (m) nz0 = 1;
            if (~m) nz1 = 1;
        }
    }

    #pragma unroll
    for (int o = 16; o > 0; o >>= 1) {
        s0 += __shfl_down_sync(0xffffffffu, s0, o);
        sp += __shfl_down_sync(0xffffffffu, sp, o);
    }
    __shared__ float sh0[8], shp[8];
    __shared__ int shfg;
    if (tid == 0) shfg = 0;
    __syncthreads();
    if (lane == 0) {
        sh0[warp] = s0; shp[warp] = sp;
        if (fg) atomicAdd(&shfg, fg);
        if (nz0) g_flag[0][0] = 1;
        if (nz1) g_flag[0][1] = 1;
    }
    __syncthreads();
    if (tid == 0) {
        float t0 = 0.0f, tp = 0.0f;
        #pragma unroll
        for (int w = 0; w < 8; w++) { t0 += sh0[w]; tp += shp[w]; }
        atomicAdd(&g_S0[b], (double)t0);
        atomicAdd(&g_Sp[b], (double)tp);
        if (shfg) atomicAdd(&g_fg[b], shfg);
    }
}

// Fused 4-iteration erosion for one field. One block per (field, b, z-tile,
// y-tile). Shared-memory double buffer with halo 4. Accumulates the
// p-weighted popcount of the alive set at each of its 4 iterations over the
// block's ownership region. Early-terminates dead tiles.
__global__ void __launch_bounds__(256) k_erode4(const float* __restrict__ inp,
                                                int group) {
    __shared__ unsigned long long bufA[TW], bufB[TW];
    __shared__ float shs[8];

    int f = blockIdx.x / BLOCKS_PER_F;
    if (g_flag[group][f] == 0) return;   // previous stage empty -> stays empty

    int rem = blockIdx.x % BLOCKS_PER_F;
    int b  = rem / TILES_PER_B;
    int t  = rem % TILES_PER_B;
    int tz = t / TILES_Y, ty = t % TILES_Y;
    int z0 = tz * ZT, y0 = ty * YT;

    int src = group & 1, dst = src ^ 1;
    const unsigned long long* gsrc = g_bits[src][f];
    unsigned long long*       gdst = g_bits[dst][f];

    int tid = threadIdx.x;

    // Load tile + halo; out-of-domain rows are all-ones (inf padding neutral).
    for (int i = tid; i < TW; i += 256) {
        int k  = i % WX;
        int rr = i / WX;
        int dy = rr % SY;
        int dz = rr / SY;
        int z = z0 + dz - H, y = y0 + dy - H;
        unsigned long long v = ~0ULL;
        if ((unsigned)z < (unsigned)Zd && (unsigned)y < (unsigned)Yd)
            v = gsrc[((long)(b * Zd + z) * Yd + y) * WX + k];
        bufA[i] = v;
    }
    __syncthreads();

    unsigned long long* cur = bufA;
    unsigned long long* nxt = bufB;
    float s = 0.0f;
    bool dead = false;
    int ownAny = 0;

    for (int j = 1; j <= 4; j++) {
        int W  = SY - 2 * j;
        int Rj = (SZ - 2 * j) * W * WX;
        int alive = 0, ownAlive = 0;

        for (int i = tid; i < Rj; i += 256) {
            int k  = i % WX;
            int rr = i / WX;
            int dy = j + rr % W;
            int dz = j + rr / W;
            int z = z0 + dz - H, y = y0 + dy - H;
            bool indom = ((unsigned)z < (unsigned)Zd) &&
                         ((unsigned)y < (unsigned)Yd);
            unsigned long long acc = ~0ULL;
            if (indom) {
                #pragma unroll
                for (int dz2 = -1; dz2 <= 1; dz2++) {
                    #pragma unroll
                    for (int dy2 = -1; dy2 <= 1; dy2++) {
                        const unsigned long long* row =
                            cur + ((dz + dz2) * SY + (dy + dy2)) * WX;
                        unsigned long long c  = row[k];
                        unsigned long long lt = (k > 0)  ? row[k - 1] : ~0ULL;
                        unsigned long long rt = (k < 2)  ? row[k + 1] : ~0ULL;
                        acc &= c & ((c >> 1) | (rt << 63))
                                 & ((c << 1) | (lt >> 63));
                    }
                }
                if (acc) {
                    alive = 1;
                    bool own = (dz >= H && dz < H + ZT &&
                                dy >= H && dy < H + YT);
                    if (own) {
                        ownAlive = 1;
                        long in0 = (long)(b * 2) * BVOX + (long)z * YX
                                 + (long)y * Xd + k * 64;
                        unsigned long long mm = acc;
                        while (mm) {
                            int bit = __ffsll((long long)mm) - 1;
                            mm &= mm - 1;
                            s += sig_p(inp[in0 + bit], inp[in0 + BVOX + bit]);
                        }
                    }
                }
            }
            nxt[(dz * SY + dy) * WX + k] = acc;
        }

        int any = __syncthreads_or(alive);
        if (j == 4) ownAny = __syncthreads_or(ownAlive);
        unsigned long long* tmp = cur; cur = nxt; nxt = tmp;
        if (!any) { dead = true; break; }
    }

    // Write ownership region of the final bitmap.
    for (int i = tid; i < ZT * YT * WX; i += 256) {
        int k  = i % WX;
        int rr = i / WX;
        int dy = H + rr % YT;
        int dz = H + rr / YT;
        int z = z0 + dz - H, y = y0 + dy - H;
        unsigned long long v = dead ? 0ULL : cur[(dz * SY + dy) * WX + k];
        gdst[((long)(b * Zd + z) * Yd + y) * WX + k] = v;
    }

    if (!dead && ownAny && tid == 0) g_flag[group + 1][f] = 1;

    // Block-reduce s and accumulate.
    int lane = tid & 31, warp = tid >> 5;
    #pragma unroll
    for (int o = 16; o > 0; o >>= 1)
        s += __shfl_down_sync(0xffffffffu, s, o);
    if (lane == 0) shs[warp] = s;
    __syncthreads();
    if (tid == 0) {
        float tot = 0.0f;
        #pragma unroll
        for (int w = 0; w < 8; w++) tot += shs[w];
        if (tot != 0.0f)
            atomicAdd(f ? &g_accB[b] : &g_accA[b], (double)tot);
    }
}

__global__ void k_final(float* out) {
    if (threadIdx.x == 0) {
        double tot = 0.0;
        #pragma unroll
        for (int b = 0; b < Bn; b++) {
            double v = (g_fg[b] == 0) ? g_Sp[b]
                                      : (g_S0[b] - g_accA[b] + g_accB[b]);
            tot += v;
        }
        out[0] = (float)(tot / (double)NVOX);
    }
}

extern "C" void kernel_launch(void* const* d_in, const int* in_sizes, int n_in,
                              void* d_out, int out_size) {
    // inputs (2*NVOX floats) first, targets (NVOX ints) second; guard by size.
    const float* inp;
    const int*   tgt;
    if (in_sizes[0] >= in_sizes[1]) {
        inp = (const float*)d_in[0];
        tgt = (const int*)d_in[1];
    } else {
        inp = (const float*)d_in[1];
        tgt = (const int*)d_in[0];
    }

    k_zero<<<1, 64>>>();
    k_pack<<<PACK_BLOCKS, 256>>>(inp, tgt);
    for (int g = 0; g < NGROUPS; g++)
        k_erode4<<<2 * BLOCKS_PER_F, 256>>>(inp, g);
    k_final<<<1, 32>>>((float*)d_out);
}